// round 17
// baseline (speedup 1.0000x reference)
#include <cuda_runtime.h>
#include <cuda_bf16.h>
#include <math.h>
#include <stdint.h>

#define NN 512
#define DD 128
#define NROWS (NN*NN)
typedef unsigned long long ull;

// ---- scratch (device globals; allocation is forbidden) ----
__device__ float g_x[NROWS*DD];                 // tri planar [d][i*NN+j]
__device__ float g_og[NROWS*DD];                // out_gate [row][d]
__device__ __nv_bfloat16 g_to_hi[(size_t)DD*NROWS];
__device__ __nv_bfloat16 g_to_lo[(size_t)DD*NROWS];
__device__ __nv_bfloat16 g_fr_hi[(size_t)DD*NROWS];
__device__ __nv_bfloat16 g_fr_lo[(size_t)DD*NROWS];
// Pre-split, pre-swizzled W smem images: tiles 0..3 = fg pairs, 4 = go, 5 = Wout.
__device__ __align__(16) unsigned char g_wimg[6*65536];
__device__ int g_mode;

static __device__ __forceinline__ float sigm(float x) { return 1.0f / (1.0f + __expf(-x)); }

static __device__ __forceinline__ uint32_t smem_u32(const void* p) {
    uint32_t a;
    asm("{ .reg .u64 t; cvta.to.shared.u64 t, %1; cvt.u32.u64 %0, t; }" : "=r"(a) : "l"(p));
    return a;
}
static __device__ __forceinline__ uint32_t pkbf(__nv_bfloat16 a, __nv_bfloat16 b) {
    __nv_bfloat162 t; t.x = a; t.y = b;
    return *(uint32_t*)&t;
}

// ---- baseline-PTX tensor + async ops ----
static __device__ __forceinline__ void ldsm_x4(uint32_t* r, uint32_t addr) {
    asm volatile("ldmatrix.sync.aligned.m8n8.x4.shared.b16 {%0,%1,%2,%3}, [%4];"
                 : "=r"(r[0]), "=r"(r[1]), "=r"(r[2]), "=r"(r[3]) : "r"(addr));
}
static __device__ __forceinline__ void mma_bf16r(float* c, const uint32_t* a, uint32_t b0, uint32_t b1) {
    asm volatile("mma.sync.aligned.m16n8k16.row.col.f32.bf16.bf16.f32 "
                 "{%0,%1,%2,%3}, {%4,%5,%6,%7}, {%8,%9}, {%0,%1,%2,%3};"
                 : "+f"(c[0]), "+f"(c[1]), "+f"(c[2]), "+f"(c[3])
                 : "r"(a[0]), "r"(a[1]), "r"(a[2]), "r"(a[3]), "r"(b0), "r"(b1));
}
static __device__ __forceinline__ void cp16(uint32_t smem, const void* gmem) {
    asm volatile("cp.async.cg.shared.global [%0], [%1], 16;" :: "r"(smem), "l"(gmem));
}
#define CP_COMMIT() asm volatile("cp.async.commit_group;" ::: "memory")
#define CP_WAIT(N)  asm volatile("cp.async.wait_group %0;" :: "n"(N) : "memory")

// ---- mask dtype detection: 0=u8, 1=i32, 2=f32, 3=bf16 ----
__global__ void k_detect(const unsigned int* __restrict__ m) {
    __shared__ int c[4];
    int t = threadIdx.x;
    if (t < 4) c[t] = 0;
    __syncthreads();
    int cb = 0, cf = 0, ci = 0, co = 0;
    for (int i = t; i < 65536; i += 256) {
        unsigned v = m[i];
        if (!v) continue;
        if (v == 0x3F803F80u || v == 0x00003F80u) cb++;
        else if (v == 0x3F800000u) cf++;
        else if (v == 1u) ci++;
        else co++;
    }
    atomicAdd(&c[0], cb); atomicAdd(&c[1], cf); atomicAdd(&c[2], ci); atomicAdd(&c[3], co);
    __syncthreads();
    if (t == 0) {
        int mode;
        if      (c[0] > 64) mode = 3;
        else if (c[3] > 64) mode = 0;
        else if (c[1] > 64) mode = 2;
        else                mode = 1;
        g_mode = mode;
    }
}
static __device__ __forceinline__ float mask_at(const void* m, int mode, int idx) {
    if (mode == 2) return ((const float*)m)[idx] != 0.0f ? 1.0f : 0.0f;
    if (mode == 0) return ((const unsigned char*)m)[idx] ? 1.0f : 0.0f;
    if (mode == 1) return ((const int*)m)[idx] ? 1.0f : 0.0f;
    return ((const unsigned short*)m)[idx] ? 1.0f : 0.0f;
}

// ---- W split precompute ----
__global__ __launch_bounds__(256) void k_wsplit(const float* __restrict__ Wfg,
                                                const float* __restrict__ Wgo,
                                                const float* __restrict__ Wout) {
    const int tile = blockIdx.x;
    const int tid = threadIdx.x;
    unsigned char* base = g_wimg + (size_t)tile * 65536;
    #pragma unroll
    for (int p = 0; p < 16; p++) {
        int idx = tid + 256 * p;
        int j = idx >> 5;
        int c4 = idx & 31;
        const float* src;
        if (tile < 4) {
            int pr = j >> 1;
            int e = (j & 1) ? (256 + tile * 64 + pr) : (tile * 64 + pr);
            src = Wfg + (size_t)e * DD;
        } else if (tile == 4) {
            src = Wgo + (size_t)j * DD;
        } else {
            src = Wout + (size_t)j * DD;
        }
        float4 v = *(const float4*)(src + c4 * 4);
        __nv_bfloat16 h0 = __float2bfloat16(v.x), h1 = __float2bfloat16(v.y);
        __nv_bfloat16 h2 = __float2bfloat16(v.z), h3 = __float2bfloat16(v.w);
        __nv_bfloat16 l0 = __float2bfloat16(v.x - __bfloat162float(h0));
        __nv_bfloat16 l1 = __float2bfloat16(v.y - __bfloat162float(h1));
        __nv_bfloat16 l2 = __float2bfloat16(v.z - __bfloat162float(h2));
        __nv_bfloat16 l3 = __float2bfloat16(v.w - __bfloat162float(h3));
        int hh = c4 >> 4;
        int c16 = (c4 & 15) >> 1;
        int sub = (c4 & 1) * 8;
        uint32_t off = (j << 7) + (c16 << 4);
        off ^= (off >> 3) & 0x70;
        *(uint2*)(base + hh * 16384 + off + sub)         = make_uint2(pkbf(h0, h1), pkbf(h2, h3));
        *(uint2*)(base + 32768 + hh * 16384 + off + sub) = make_uint2(pkbf(l0, l1), pkbf(l2, l3));
    }
}

// ---- Stage 2: LN1 + fused projection, 512 threads / 16 warps ----
// smem: x hi [0,32KB), x lo [32KB,64KB), W double buffer at 64KB / 128KB.
#define FG_SMEM (65536 + 2*65536)
__global__ __launch_bounds__(512) void k_fg(const float* __restrict__ edges,
                                            const void*  __restrict__ mask,
                                            const float* __restrict__ ln1w,
                                            const float* __restrict__ ln1b,
                                            const float* __restrict__ bfg,
                                            const float* __restrict__ bgo) {
    extern __shared__ char smc[];
    const uint32_t sb = smem_u32(smc);
    const int tid = threadIdx.x;
    const int wid = tid >> 5, lane = tid & 31;
    const int row0 = blockIdx.x * 128;
    const int mode = g_mode;
    const int wm = wid >> 1, wn = wid & 1;   // 8 m-warps x 2 n-warps

    // W0 / W1 prefetch first (overlaps the LN below)
    #pragma unroll
    for (int p = 0; p < 8; p++) {
        int idx = tid + 512 * p;
        cp16(sb + 65536 + idx * 16, g_wimg + idx * 16);
    }
    CP_COMMIT();
    #pragma unroll
    for (int p = 0; p < 8; p++) {
        int idx = tid + 512 * p;
        cp16(sb + 131072 + idx * 16, g_wimg + 65536 + idx * 16);
    }
    CP_COMMIT();

    // LN1 for this CTA's 128 rows: warp handles 8 rows, lane covers d = lane*4..+3.
    // bf16 hi/lo written straight into swizzled x smem tiles.
    {
        float w4[4], b4[4];
        #pragma unroll
        for (int q = 0; q < 4; q++) { w4[q] = ln1w[lane * 4 + q]; b4[q] = ln1b[lane * 4 + q]; }
        int dd = lane * 4;
        int hh = dd >> 6;
        uint32_t offb = (uint32_t)((dd & 63) * 2);
        #pragma unroll
        for (int rr = 0; rr < 8; rr++) {
            int row = wid * 8 + rr;
            float4 v = *(const float4*)&edges[(size_t)(row0 + row) * DD + dd];
            float s = v.x + v.y + v.z + v.w;
            float q2 = v.x * v.x + v.y * v.y + v.z * v.z + v.w * v.w;
            #pragma unroll
            for (int o = 16; o; o >>= 1) {
                s  += __shfl_xor_sync(0xffffffffu, s, o);
                q2 += __shfl_xor_sync(0xffffffffu, q2, o);
            }
            float mu = s * (1.0f / DD);
            float var = q2 * (1.0f / DD) - mu * mu;
            float rs = rsqrtf(var + 1e-5f);
            float n0 = (v.x - mu) * rs * w4[0] + b4[0];
            float n1 = (v.y - mu) * rs * w4[1] + b4[1];
            float n2 = (v.z - mu) * rs * w4[2] + b4[2];
            float n3 = (v.w - mu) * rs * w4[3] + b4[3];
            __nv_bfloat16 h0 = __float2bfloat16(n0), h1 = __float2bfloat16(n1);
            __nv_bfloat16 h2 = __float2bfloat16(n2), h3 = __float2bfloat16(n3);
            __nv_bfloat16 l0 = __float2bfloat16(n0 - __bfloat162float(h0));
            __nv_bfloat16 l1 = __float2bfloat16(n1 - __bfloat162float(h1));
            __nv_bfloat16 l2 = __float2bfloat16(n2 - __bfloat162float(h2));
            __nv_bfloat16 l3 = __float2bfloat16(n3 - __bfloat162float(h3));
            uint32_t off = ((uint32_t)row << 7) + offb;
            off ^= (off >> 3) & 0x70;
            *(uint2*)(smc + hh * 16384 + off)         = make_uint2(pkbf(h0, h1), pkbf(h2, h3));
            *(uint2*)(smc + 32768 + hh * 16384 + off) = make_uint2(pkbf(l0, l1), pkbf(l2, l3));
        }
    }

    #pragma unroll 1
    for (int nt = 0; nt < 5; nt++) {
        if (nt < 4) { CP_WAIT(1); } else { CP_WAIT(0); }
        __syncthreads();
        const uint32_t wb = sb + 65536 + (uint32_t)(nt & 1) * 65536;

        float acc[8][4];
        #pragma unroll
        for (int nf = 0; nf < 8; nf++)
            #pragma unroll
            for (int q = 0; q < 4; q++) acc[nf][q] = 0.0f;

        #pragma unroll
        for (int ks = 0; ks < 8; ks++) {
            int h = ks >> 2, kk = ks & 3;
            uint32_t b_hi[4][4], b_lo[4][4];
            #pragma unroll
            for (int nfp = 0; nfp < 4; nfp++) {
                uint32_t row = (uint32_t)(wn * 64 + nfp * 16 + ((lane >> 3) & 1) * 8 + (lane & 7));
                uint32_t off = (row << 7) + ((uint32_t)kk << 5) + ((uint32_t)(lane >> 4) << 4);
                off ^= (off >> 3) & 0x70;
                ldsm_x4(b_hi[nfp], wb + h * 16384 + off);
                ldsm_x4(b_lo[nfp], wb + 32768 + h * 16384 + off);
            }
            uint32_t a_hi[4], a_lo[4];
            {
                uint32_t row = (uint32_t)(wm * 16 + (lane & 15));
                uint32_t off = (row << 7) + ((uint32_t)kk << 5) + ((uint32_t)(lane >> 4) << 4);
                off ^= (off >> 3) & 0x70;
                ldsm_x4(a_hi, sb + h * 16384 + off);
                ldsm_x4(a_lo, sb + 32768 + h * 16384 + off);
            }
            #pragma unroll
            for (int nfp = 0; nfp < 4; nfp++) {
                mma_bf16r(acc[2*nfp],   a_hi, b_hi[nfp][0], b_hi[nfp][2]);
                mma_bf16r(acc[2*nfp],   a_hi, b_lo[nfp][0], b_lo[nfp][2]);
                mma_bf16r(acc[2*nfp],   a_lo, b_hi[nfp][0], b_hi[nfp][2]);
                mma_bf16r(acc[2*nfp+1], a_hi, b_hi[nfp][1], b_hi[nfp][3]);
                mma_bf16r(acc[2*nfp+1], a_hi, b_lo[nfp][1], b_lo[nfp][3]);
                mma_bf16r(acc[2*nfp+1], a_lo, b_hi[nfp][1], b_hi[nfp][3]);
            }
        }

        // free the consumed W buffer, start next prefetch BEFORE the epilogue
        __syncthreads();
        if (nt + 2 <= 4) {
            const unsigned char* src = g_wimg + (size_t)(nt + 2) * 65536;
            uint32_t dst = sb + 65536 + (uint32_t)(nt & 1) * 65536;
            #pragma unroll
            for (int p = 0; p < 8; p++) {
                int idx = tid + 512 * p;
                cp16(dst + idx * 16, src + idx * 16);
            }
            CP_COMMIT();
        }

        int r = row0 + wm * 16 + (lane >> 2);
        float mv0 = mask_at(mask, mode, r);
        float mv1 = mask_at(mask, mode, r + 8);
        if (nt < 4) {
            #pragma unroll
            for (int nf = 0; nf < 8; nf++) {
                int f = nt * 64 + wn * 32 + nf * 4 + (lane & 3);
                float bf = bfg[f], bg = bfg[256 + f];
                __nv_bfloat16* ph; __nv_bfloat16* pl;
                if (f < 128) { ph = g_to_hi + (size_t)f * NROWS;         pl = g_to_lo + (size_t)f * NROWS; }
                else         { ph = g_fr_hi + (size_t)(f - 128) * NROWS; pl = g_fr_lo + (size_t)(f - 128) * NROWS; }
                float v0 = (acc[nf][0] + bf) * sigm(acc[nf][1] + bg) * mv0;
                float v1 = (acc[nf][2] + bf) * sigm(acc[nf][3] + bg) * mv1;
                __nv_bfloat16 h0 = __float2bfloat16(v0);
                __nv_bfloat16 l0 = __float2bfloat16(v0 - __bfloat162float(h0));
                __nv_bfloat16 h1 = __float2bfloat16(v1);
                __nv_bfloat16 l1 = __float2bfloat16(v1 - __bfloat162float(h1));
                ph[r] = h0;     pl[r] = l0;
                ph[r + 8] = h1; pl[r + 8] = l1;
            }
        } else {
            #pragma unroll
            for (int nf = 0; nf < 8; nf++) {
                int e = wn * 64 + nf * 8 + (lane & 3) * 2;
                float b0 = bgo[e], b1 = bgo[e + 1];
                *(float2*)&g_og[(size_t)r * DD + e] =
                    make_float2(sigm(acc[nf][0] + b0) * mv0, sigm(acc[nf][1] + b1) * mv0);
                *(float2*)&g_og[(size_t)(r + 8) * DD + e] =
                    make_float2(sigm(acc[nf][2] + b0) * mv1, sigm(acc[nf][3] + b1) * mv1);
            }
        }
    }
}

// ---- Stage 3: tri via HMMA + cp.async double buffering (B x4 pairing) ----
#define TRI_SMEM 65536
static __device__ __forceinline__ uint32_t sw64(uint32_t row, uint32_t chunk) {
    return (row << 6) + (((chunk ^ (row >> 1)) & 3) << 4);
}
__global__ __launch_bounds__(256, 2) void k_tri() {
    extern __shared__ char smc[];
    const uint32_t sb = smem_u32(smc);
    const int tid = threadIdx.x;
    const int wid = tid >> 5, lane = tid & 31;
    const int j0 = blockIdx.x * 128, i0 = blockIdx.y * 128, d = blockIdx.z;
    const int wm = wid >> 2, wn = wid & 3;

    float acc[4][4][4];
    #pragma unroll
    for (int mt = 0; mt < 4; mt++)
        #pragma unroll
        for (int nt = 0; nt < 4; nt++)
            #pragma unroll
            for (int q = 0; q < 4; q++) acc[mt][nt][q] = 0.0f;

    const __nv_bfloat16* srcs[4] = {
        g_to_hi + (size_t)d * NROWS + (size_t)i0 * NN,
        g_to_lo + (size_t)d * NROWS + (size_t)i0 * NN,
        g_fr_hi + (size_t)d * NROWS + (size_t)j0 * NN,
        g_fr_lo + (size_t)d * NROWS + (size_t)j0 * NN
    };

    auto load_slab = [&](int kp, int buf) {
        uint32_t bb = sb + buf * 32768;
        #pragma unroll
        for (int p = 0; p < 8; p++) {
            int idx = tid + 256 * p;
            int t = idx >> 9;
            int r = (idx >> 2) & 127;
            int c = idx & 3;
            cp16(bb + t * 8192 + sw64(r, c), srcs[t] + (size_t)r * NN + kp * 32 + c * 8);
        }
        CP_COMMIT();
    };

    load_slab(0, 0);
    for (int kp = 0; kp < 16; kp++) {
        if (kp < 15) {
            load_slab(kp + 1, (kp + 1) & 1);
            CP_WAIT(1);
        } else {
            CP_WAIT(0);
        }
        __syncthreads();

        uint32_t bb = sb + (kp & 1) * 32768;
        #pragma unroll
        for (int ks = 0; ks < 2; ks++) {
            uint32_t b_hi[2][4], b_lo[2][4];
            #pragma unroll
            for (int ntp = 0; ntp < 2; ntp++) {
                uint32_t row = (uint32_t)(wn * 32 + ntp * 16 + ((lane >> 3) & 1) * 8 + (lane & 7));
                uint32_t chunk = (uint32_t)(ks * 2 + (lane >> 4));
                ldsm_x4(b_hi[ntp], bb + 16384 + sw64(row, chunk));
                ldsm_x4(b_lo[ntp], bb + 24576 + sw64(row, chunk));
            }
            #pragma unroll
            for (int mt = 0; mt < 4; mt++) {
                uint32_t a_hi[4], a_lo[4];
                uint32_t off = sw64((uint32_t)(wm * 64 + mt * 16 + (lane & 15)),
                                    (uint32_t)(ks * 2 + (lane >> 4)));
                ldsm_x4(a_hi, bb + off);
                ldsm_x4(a_lo, bb + 8192 + off);
                #pragma unroll
                for (int ntp = 0; ntp < 2; ntp++) {
                    mma_bf16r(acc[mt][2*ntp],   a_hi, b_hi[ntp][0], b_hi[ntp][2]);
                    mma_bf16r(acc[mt][2*ntp],   a_hi, b_lo[ntp][0], b_lo[ntp][2]);
                    mma_bf16r(acc[mt][2*ntp],   a_lo, b_hi[ntp][0], b_hi[ntp][2]);
                    mma_bf16r(acc[mt][2*ntp+1], a_hi, b_hi[ntp][1], b_hi[ntp][3]);
                    mma_bf16r(acc[mt][2*ntp+1], a_hi, b_lo[ntp][1], b_lo[ntp][3]);
                    mma_bf16r(acc[mt][2*ntp+1], a_lo, b_hi[ntp][1], b_hi[ntp][3]);
                }
            }
        }
        __syncthreads();
    }

    #pragma unroll
    for (int mt = 0; mt < 4; mt++) {
        int i = i0 + wm * 64 + mt * 16 + (lane >> 2);
        #pragma unroll
        for (int nt = 0; nt < 4; nt++) {
            int j = j0 + wn * 32 + nt * 8 + (lane & 3) * 2;
            size_t base = (size_t)d * NROWS + (size_t)i * NN + j;
            *(float2*)&g_x[base]          = make_float2(acc[mt][nt][0], acc[mt][nt][1]);
            *(float2*)&g_x[base + 8 * NN] = make_float2(acc[mt][nt][2], acc[mt][nt][3]);
        }
    }
}

// ---- Stage 4: LN2 -> bf16 split -> HMMA, times out_gate; 512 threads ----
#define OUT_SMEM (131072 + 128*133*4)
__global__ __launch_bounds__(512) void k_out(const float* __restrict__ ln2w,
                                             const float* __restrict__ ln2b,
                                             const float* __restrict__ bout,
                                             float* __restrict__ out) {
    extern __shared__ char smc[];
    const uint32_t sb = smem_u32(smc);
    float* ys = (float*)(smc + 131072);
    const int tid = threadIdx.x;
    const int wid = tid >> 5, lane = tid & 31;
    const int row0 = blockIdx.x * 128;
    const int wm = wid >> 1, wn = wid & 1;

    #pragma unroll
    for (int p = 0; p < 8; p++) {
        int idx = tid + 512 * p;
        cp16(sb + 65536 + idx * 16, g_wimg + 5 * 65536 + idx * 16);
    }
    CP_COMMIT();

    #pragma unroll 8
    for (int p = 0; p < 32; p++) {
        int idx = tid + 512 * p;
        int row = idx & 127, dd = idx >> 7;
        ys[row * 133 + dd] = g_x[(size_t)dd * NROWS + row0 + row];
    }
    __syncthreads();

    {
        float w4[4], b4[4];
        #pragma unroll
        for (int q = 0; q < 4; q++) { w4[q] = ln2w[lane * 4 + q]; b4[q] = ln2b[lane * 4 + q]; }
        int dd = lane * 4;
        int hh = dd >> 6;
        uint32_t offb = (uint32_t)((dd & 63) * 2);
        #pragma unroll
        for (int rr = 0; rr < 8; rr++) {
            int row = wid * 8 + rr;
            float* yr = &ys[row * 133 + dd];
            float v0 = yr[0], v1 = yr[1], v2 = yr[2], v3 = yr[3];
            float s = v0 + v1 + v2 + v3;
            float q2 = v0 * v0 + v1 * v1 + v2 * v2 + v3 * v3;
            #pragma unroll
            for (int o = 16; o; o >>= 1) {
                s  += __shfl_xor_sync(0xffffffffu, s, o);
                q2 += __shfl_xor_sync(0xffffffffu, q2, o);
            }
            float mu = s * (1.0f / DD);
            float var = q2 * (1.0f / DD) - mu * mu;
            float rs = rsqrtf(var + 1e-5f);
            float n0 = (v0 - mu) * rs * w4[0] + b4[0];
            float n1 = (v1 - mu) * rs * w4[1] + b4[1];
            float n2 = (v2 - mu) * rs * w4[2] + b4[2];
            float n3 = (v3 - mu) * rs * w4[3] + b4[3];
            __nv_bfloat16 h0 = __float2bfloat16(n0), h1 = __float2bfloat16(n1);
            __nv_bfloat16 h2 = __float2bfloat16(n2), h3 = __float2bfloat16(n3);
            __nv_bfloat16 l0 = __float2bfloat16(n0 - __bfloat162float(h0));
            __nv_bfloat16 l1 = __float2bfloat16(n1 - __bfloat162float(h1));
            __nv_bfloat16 l2 = __float2bfloat16(n2 - __bfloat162float(h2));
            __nv_bfloat16 l3 = __float2bfloat16(n3 - __bfloat162float(h3));
            uint32_t off = ((uint32_t)row << 7) + offb;
            off ^= (off >> 3) & 0x70;
            *(uint2*)(smc + hh * 16384 + off)         = make_uint2(pkbf(h0, h1), pkbf(h2, h3));
            *(uint2*)(smc + 32768 + hh * 16384 + off) = make_uint2(pkbf(l0, l1), pkbf(l2, l3));
        }
    }
    CP_WAIT(0);
    __syncthreads();

    float acc[8][4];
    #pragma unroll
    for (int nf = 0; nf < 8; nf++)
        #pragma unroll
        for (int q = 0; q < 4; q++) acc[nf][q] = 0.0f;

    #pragma unroll
    for (int ks = 0; ks < 8; ks++) {
        int h = ks >> 2, kk = ks & 3;
        uint32_t b_hi[4][4], b_lo[4][4];
        #pragma unroll
        for (int nfp = 0; nfp < 4; nfp++) {
            uint32_t row = (uint32_t)(wn * 64 + nfp * 16 + ((lane >> 3) & 1) * 8 + (lane & 7));
            uint32_t off = (row << 7) + ((uint32_t)kk << 5) + ((uint32_t)(lane >> 4) << 4);
            off ^= (off >> 3) & 0x70;
            ldsm_x4(b_hi[nfp], sb + 65536 + h * 16384 + off);
            ldsm_x4(b_lo[nfp], sb + 98304 + h * 16384 + off);
        }
        uint32_t a_hi[4], a_lo[4];
        {
            uint32_t row = (uint32_t)(wm * 16 + (lane & 15));
            uint32_t off = (row << 7) + ((uint32_t)kk << 5) + ((uint32_t)(lane >> 4) << 4);
            off ^= (off >> 3) & 0x70;
            ldsm_x4(a_hi, sb + h * 16384 + off);
            ldsm_x4(a_lo, sb + 32768 + h * 16384 + off);
        }
        #pragma unroll
        for (int nfp = 0; nfp < 4; nfp++) {
            mma_bf16r(acc[2*nfp],   a_hi, b_hi[nfp][0], b_hi[nfp][2]);
            mma_bf16r(acc[2*nfp],   a_hi, b_lo[nfp][0], b_lo[nfp][2]);
            mma_bf16r(acc[2*nfp],   a_lo, b_hi[nfp][0], b_hi[nfp][2]);
            mma_bf16r(acc[2*nfp+1], a_hi, b_hi[nfp][1], b_hi[nfp][3]);
            mma_bf16r(acc[2*nfp+1], a_hi, b_lo[nfp][1], b_lo[nfp][3]);
            mma_bf16r(acc[2*nfp+1], a_lo, b_hi[nfp][1], b_hi[nfp][3]);
        }
    }

    int r = row0 + wm * 16 + (lane >> 2);
    #pragma unroll
    for (int nf = 0; nf < 8; nf++) {
        int col = wn * 64 + nf * 8 + (lane & 3) * 2;
        float b0 = bout[col], b1 = bout[col + 1];
        size_t base = (size_t)r * DD + col;
        float2 og0 = *(const float2*)&g_og[base];
        *(float2*)&out[base] = make_float2(og0.x * (acc[nf][0] + b0),
                                           og0.y * (acc[nf][1] + b1));
        float2 og1 = *(const float2*)&g_og[base + 8 * DD];
        *(float2*)&out[base + 8 * DD] = make_float2(og1.x * (acc[nf][2] + b0),
                                                    og1.y * (acc[nf][3] + b1));
    }
}

extern "C" void kernel_launch(void* const* d_in, const int* in_sizes, int n_in,
                              void* d_out, int out_size) {
    const float* edges = (const float*)d_in[0];
    const void*  mask  = d_in[1];
    const float* ln1w  = (const float*)d_in[2];
    const float* ln1b  = (const float*)d_in[3];
    const float* Wfg   = (const float*)d_in[4];
    const float* bfg   = (const float*)d_in[5];
    const float* Wgo   = (const float*)d_in[6];
    const float* bgo   = (const float*)d_in[7];
    const float* ln2w  = (const float*)d_in[8];
    const float* ln2b  = (const float*)d_in[9];
    const float* Wout  = (const float*)d_in[10];
    const float* bout  = (const float*)d_in[11];
    float* out = (float*)d_out;

    cudaFuncSetAttribute(k_fg,  cudaFuncAttributeMaxDynamicSharedMemorySize, FG_SMEM);
    cudaFuncSetAttribute(k_tri, cudaFuncAttributeMaxDynamicSharedMemorySize, TRI_SMEM);
    cudaFuncSetAttribute(k_out, cudaFuncAttributeMaxDynamicSharedMemorySize, OUT_SMEM);

    k_detect<<<1, 256>>>((const unsigned int*)mask);
    k_wsplit<<<6, 256>>>(Wfg, Wgo, Wout);
    k_fg<<<NROWS / 128, 512, FG_SMEM>>>(edges, mask, ln1w, ln1b, bfg, bgo);
    k_tri<<<dim3(NN / 128, NN / 128, DD), 256, TRI_SMEM>>>();
    k_out<<<NROWS / 128, 512, OUT_SMEM>>>(ln2w, ln2b, bout, out);
}